// round 12
// baseline (speedup 1.0000x reference)
#include <cuda_runtime.h>

#define BATCH   8
#define NDATA   8192
#define NPOINT  1024
#define NSAMPLE 32
#define CFEAT   64
#define RADIUSF 0.2f
#define T_LOOSE 0.0404f

#define NP_SIZE  (BATCH*NPOINT*NSAMPLE*(3+CFEAT))   /* 17563648 */
#define IDX_OFF  NP_SIZE
#define IDX_SIZE (BATCH*NPOINT*NSAMPLE)             /* 262144 */
#define GX_OFF   (IDX_OFF + IDX_SIZE)

#define QB  16   /* queries per block             */
#define WPB 8    /* warps per block (scan chunks) */
#define CHUNK (NDATA/WPB)                           /* 1024 */
#define CAP 64   /* candidate capacity per query  */

#define ROWS_PB 64                                  /* rows per gather block */
#define RPG     (ROWS_PB/4)                         /* 16 rows per 64-thread group */

__device__ float4 g_pts[BATCH*NDATA];   /* (x, y, z, |p|^2) */

__global__ void k_transpose(const float* __restrict__ xyz)
{
    int t = blockIdx.x * blockDim.x + threadIdx.x;
    if (t < BATCH*NDATA) {
        float x = xyz[3*t + 0];
        float y = xyz[3*t + 1];
        float z = xyz[3*t + 2];
        float pp = fmaf(x, x, fmaf(y, y, z*z));
        g_pts[t] = make_float4(x, y, z, pp);
    }
}

__global__ __launch_bounds__(WPB*32)
void k_search(const float* __restrict__ new_xyz, float* __restrict__ out)
{
    __shared__ float s_cd[QB][CAP];
    __shared__ int   s_ci[QB][CAP];
    __shared__ int   s_cnt[QB];
    __shared__ int   s_out[QB][NSAMPLE];
    __shared__ float s_qx[QB], s_qy[QB], s_qz[QB];

    const int b    = blockIdx.y;
    const int w    = threadIdx.x >> 5;
    const int lane = threadIdx.x & 31;
    const int p0   = blockIdx.x * QB;

    if (threadIdx.x < QB) {
        s_cnt[threadIdx.x] = 0;
        const float* qp = new_xyz + ((size_t)b*NPOINT + p0 + threadIdx.x) * 3;
        s_qx[threadIdx.x] = qp[0];
        s_qy[threadIdx.x] = qp[1];
        s_qz[threadIdx.x] = qp[2];
    }
    __syncthreads();

    float nqx[QB], nqy[QB], nqz[QB], qt[QB];
#pragma unroll
    for (int q = 0; q < QB; q++) {
        float cx = s_qx[q], cy = s_qy[q], cz = s_qz[q];
        nqx[q] = -2.0f*cx; nqy[q] = -2.0f*cy; nqz[q] = -2.0f*cz;
        qt[q] = T_LOOSE - fmaf(cx,cx, fmaf(cy,cy, cz*cz));
    }

    const float4* pts = g_pts + b*NDATA;

    const int ptEnd = (w+1)*CHUNK;
    for (int pt = w*CHUNK + lane; pt < ptEnd; pt += 32) {
        float4 P = pts[pt];
        unsigned m = 0;
#pragma unroll
        for (int q = 0; q < QB; q++) {
            float l = fmaf(P.x, nqx[q], fmaf(P.y, nqy[q], fmaf(P.z, nqz[q], P.w)));
            if (l < qt[q]) m |= (1u << q);
        }
        while (m) {
            int q = __ffs(m) - 1;
            m &= m - 1;
            float dx = P.x - s_qx[q];
            float dy = P.y - s_qy[q];
            float dz = P.z - s_qz[q];
            float e = __fadd_rn(__fadd_rn(__fmul_rn(dx,dx), __fmul_rn(dy,dy)),
                                __fmul_rn(dz,dz));
            float d = __fsqrt_rn(e);
            if (d < RADIUSF) {
                int slot = atomicAdd(&s_cnt[q], 1);
                if (slot < CAP) { s_cd[q][slot] = d; s_ci[q][slot] = pt; }
            }
        }
    }
    __syncthreads();

    for (int qq = 0; qq < QB/WPB; qq++) {
        const int q = w*(QB/WPB) + qq;
        const int n = min(s_cnt[q], CAP);
        const int p = p0 + q;

        if (n == 0) {
            float cx = s_qx[q], cy = s_qy[q], cz = s_qz[q];
            float bd = 3.4e38f; int bi = 0;
            for (int pt = lane; pt < NDATA; pt += 32) {
                float4 P = pts[pt];
                float dx = P.x - cx;
                float dy = P.y - cy;
                float dz = P.z - cz;
                float e  = __fadd_rn(__fadd_rn(__fmul_rn(dx,dx), __fmul_rn(dy,dy)),
                                     __fmul_rn(dz,dz));
                if (e < bd) { bd = e; bi = pt; }
            }
#pragma unroll
            for (int off = 16; off >= 1; off >>= 1) {
                float od = __shfl_xor_sync(0xffffffffu, bd, off);
                int   oi = __shfl_xor_sync(0xffffffffu, bi, off);
                if (od < bd || (od == bd && oi < bi)) { bd = od; bi = oi; }
            }
            s_out[q][lane] = bi;
        } else {
            for (int i = lane; i < n; i += 32) {
                float di = s_cd[q][i]; int ii = s_ci[q][i];
                int rank = 0;
                for (int j = 0; j < n; j++) {
                    float dj = s_cd[q][j]; int ij = s_ci[q][j];
                    rank += (dj < di) || (dj == di && ij < ii);
                }
                if (rank < NSAMPLE) s_out[q][rank] = ii;
            }
            __syncwarp();
            int nearest = s_out[q][0];
            if (lane >= n) s_out[q][lane] = nearest;
        }
        __syncwarp();

        out[IDX_OFF + ((size_t)(b*NPOINT + p))*NSAMPLE + lane] = (float)s_out[q][lane];
    }
}

// Smem-staged gather: R6-style batched loads (MLP=16), dense aligned
// STG.128 flush of both output regions.
__global__ __launch_bounds__(256)
void k_gather(const float* __restrict__ xyz,
              const float* __restrict__ points,
              float* __restrict__ out)
{
    __shared__ __align__(16) float s_np[ROWS_PB*67];   /* 17152 B */
    __shared__ __align__(16) float s_gx[ROWS_PB*3];    /*   768 B */
    __shared__ int s_id[ROWS_PB];

    const int  bid = blockIdx.x;
    const long r0  = (long)bid * ROWS_PB;
    const int  b   = bid >> 9;           /* 512 blocks per batch */
    const float* idxf = out + IDX_OFF;

    if (threadIdx.x < ROWS_PB)
        s_id[threadIdx.x] = (int)__ldg(&idxf[r0 + threadIdx.x]);
    __syncthreads();

    const int g = threadIdx.x >> 6;      /* 0..3 */
    const int c = threadIdx.x & 63;
    const float* P  = points + (size_t)b*NDATA*CFEAT;
    const float* Xb = xyz    + (size_t)b*NDATA*3;

    int ids[RPG];
#pragma unroll
    for (int u = 0; u < RPG; u++) ids[u] = s_id[g*RPG + u];

    float v[RPG];
#pragma unroll
    for (int u = 0; u < RPG; u++)
        v[u] = __ldg(&P[(size_t)ids[u]*CFEAT + c]);
#pragma unroll
    for (int u = 0; u < RPG; u++)
        s_np[(g*RPG + u)*67 + 3 + c] = v[u];

    if (c < 3) {
        float xv[RPG];
#pragma unroll
        for (int u = 0; u < RPG; u++)
            xv[u] = __ldg(&Xb[(size_t)ids[u]*3 + c]);
#pragma unroll
        for (int u = 0; u < RPG; u++) {
            s_np[(g*RPG + u)*67 + c] = xv[u];
            s_gx[(g*RPG + u)*3  + c] = xv[u];
        }
    }
    __syncthreads();

    /* dense flush: 64*67 = 4288 floats = 1072 quads; gx 192 floats = 48 quads */
    float4*       o4 = reinterpret_cast<float4*>(out + r0*67);
    const float4* s4 = reinterpret_cast<const float4*>(s_np);
#pragma unroll
    for (int k = 0; k < 4; k++) {
        int i = threadIdx.x + k*256;
        o4[i] = s4[i];
    }
    {
        int i = threadIdx.x + 4*256;
        if (i < (ROWS_PB*67)/4) o4[i] = s4[i];
    }
    float4*       og = reinterpret_cast<float4*>(out + GX_OFF + r0*3);
    const float4* sg = reinterpret_cast<const float4*>(s_gx);
    if (threadIdx.x < (ROWS_PB*3)/4) og[threadIdx.x] = sg[threadIdx.x];
}

extern "C" void kernel_launch(void* const* d_in, const int* in_sizes, int n_in,
                              void* d_out, int out_size)
{
    const float *new_xyz = nullptr, *xyz = nullptr, *points = nullptr;
    for (int i = 0; i < n_in; i++) {
        if      (in_sizes[i] == BATCH*NPOINT*3)     new_xyz = (const float*)d_in[i];
        else if (in_sizes[i] == BATCH*NDATA*3)      xyz     = (const float*)d_in[i];
        else if (in_sizes[i] == BATCH*NDATA*CFEAT)  points  = (const float*)d_in[i];
    }
    float* out = (float*)d_out;

    k_transpose<<<(BATCH*NDATA + 255)/256, 256>>>(xyz);

    dim3 gs(NPOINT/QB, BATCH);
    k_search<<<gs, WPB*32>>>(new_xyz, out);

    k_gather<<<IDX_SIZE/ROWS_PB, 256>>>(xyz, points, out);
}

// round 13
// speedup vs baseline: 1.0557x; 1.0557x over previous
#include <cuda_runtime.h>

#define BATCH   8
#define NDATA   8192
#define NPOINT  1024
#define NSAMPLE 32
#define CFEAT   64
#define RADIUSF 0.2f
#define T_LOOSE 0.0404f

#define NP_SIZE  (BATCH*NPOINT*NSAMPLE*(3+CFEAT))   /* 17563648 */
#define IDX_OFF  NP_SIZE
#define IDX_SIZE (BATCH*NPOINT*NSAMPLE)             /* 262144 */
#define GX_OFF   (IDX_OFF + IDX_SIZE)

#define QB  16   /* queries per block             */
#define WPB 8    /* warps per block (scan chunks) */
#define CHUNK (NDATA/WPB)                           /* 1024 */
#define CAP 64   /* candidate capacity per query  */

#define ROWS_PB   (QB*NSAMPLE)                      /* 512 rows per block    */
#define ROWS_PG   (ROWS_PB/4)                       /* 128 rows per group    */
#define GUNROLL   8

__device__ float4 g_pts[BATCH*NDATA];   /* (x, y, z, |p|^2) */

__global__ void k_transpose(const float* __restrict__ xyz)
{
    int t = blockIdx.x * blockDim.x + threadIdx.x;
    if (t < BATCH*NDATA) {
        float x = xyz[3*t + 0];
        float y = xyz[3*t + 1];
        float z = xyz[3*t + 2];
        float pp = fmaf(x, x, fmaf(y, y, z*z));
        g_pts[t] = make_float4(x, y, z, pp);
    }
}

__global__ __launch_bounds__(WPB*32)
void k_search(const float* __restrict__ new_xyz,
              const float* __restrict__ xyz,
              const float* __restrict__ points,
              float* __restrict__ out)
{
    __shared__ float s_cd[QB][CAP];
    __shared__ int   s_ci[QB][CAP];
    __shared__ int   s_cnt[QB];
    __shared__ int   s_out[QB*NSAMPLE];            /* flat: row-local order */
    __shared__ float s_qx[QB], s_qy[QB], s_qz[QB];

    const int b    = blockIdx.y;
    const int w    = threadIdx.x >> 5;
    const int lane = threadIdx.x & 31;
    const int p0   = blockIdx.x * QB;

    if (threadIdx.x < QB) {
        s_cnt[threadIdx.x] = 0;
        const float* qp = new_xyz + ((size_t)b*NPOINT + p0 + threadIdx.x) * 3;
        s_qx[threadIdx.x] = qp[0];
        s_qy[threadIdx.x] = qp[1];
        s_qz[threadIdx.x] = qp[2];
    }
    __syncthreads();

    float nqx[QB], nqy[QB], nqz[QB], qt[QB];
#pragma unroll
    for (int q = 0; q < QB; q++) {
        float cx = s_qx[q], cy = s_qy[q], cz = s_qz[q];
        nqx[q] = -2.0f*cx; nqy[q] = -2.0f*cy; nqz[q] = -2.0f*cz;
        qt[q] = T_LOOSE - fmaf(cx,cx, fmaf(cy,cy, cz*cz));
    }

    const float4* pts = g_pts + b*NDATA;

    /* ---- scan: branchless mask hot loop, rare slow path ----------------- */
    const int ptEnd = (w+1)*CHUNK;
    for (int pt = w*CHUNK + lane; pt < ptEnd; pt += 32) {
        float4 P = pts[pt];
        unsigned m = 0;
#pragma unroll
        for (int q = 0; q < QB; q++) {
            float l = fmaf(P.x, nqx[q], fmaf(P.y, nqy[q], fmaf(P.z, nqz[q], P.w)));
            if (l < qt[q]) m |= (1u << q);
        }
        while (m) {
            int q = __ffs(m) - 1;
            m &= m - 1;
            float dx = P.x - s_qx[q];
            float dy = P.y - s_qy[q];
            float dz = P.z - s_qz[q];
            float e = __fadd_rn(__fadd_rn(__fmul_rn(dx,dx), __fmul_rn(dy,dy)),
                                __fmul_rn(dz,dz));
            float d = __fsqrt_rn(e);
            if (d < RADIUSF) {
                int slot = atomicAdd(&s_cnt[q], 1);
                if (slot < CAP) { s_cd[q][slot] = d; s_ci[q][slot] = pt; }
            }
        }
    }
    __syncthreads();

    /* ---- rank: warp w handles queries 2w, 2w+1; writes idx region ------- */
    for (int qq = 0; qq < QB/WPB; qq++) {
        const int q = w*(QB/WPB) + qq;
        const int n = min(s_cnt[q], CAP);
        const int p = p0 + q;

        if (n == 0) {
            float cx = s_qx[q], cy = s_qy[q], cz = s_qz[q];
            float bd = 3.4e38f; int bi = 0;
            for (int pt = lane; pt < NDATA; pt += 32) {
                float4 P = pts[pt];
                float dx = P.x - cx;
                float dy = P.y - cy;
                float dz = P.z - cz;
                float e  = __fadd_rn(__fadd_rn(__fmul_rn(dx,dx), __fmul_rn(dy,dy)),
                                     __fmul_rn(dz,dz));
                if (e < bd) { bd = e; bi = pt; }
            }
#pragma unroll
            for (int off = 16; off >= 1; off >>= 1) {
                float od = __shfl_xor_sync(0xffffffffu, bd, off);
                int   oi = __shfl_xor_sync(0xffffffffu, bi, off);
                if (od < bd || (od == bd && oi < bi)) { bd = od; bi = oi; }
            }
            s_out[q*NSAMPLE + lane] = bi;
        } else {
            for (int i = lane; i < n; i += 32) {
                float di = s_cd[q][i]; int ii = s_ci[q][i];
                int rank = 0;
                for (int j = 0; j < n; j++) {
                    float dj = s_cd[q][j]; int ij = s_ci[q][j];
                    rank += (dj < di) || (dj == di && ij < ii);
                }
                if (rank < NSAMPLE) s_out[q*NSAMPLE + rank] = ii;
            }
            __syncwarp();
            int nearest = s_out[q*NSAMPLE];
            if (lane >= n) s_out[q*NSAMPLE + lane] = nearest;
        }
        __syncwarp();

        out[IDX_OFF + ((size_t)(b*NPOINT + p))*NSAMPLE + lane]
            = (float)s_out[q*NSAMPLE + lane];
    }
    __syncthreads();

    /* ---- fused gather: this block's 512 consecutive output rows --------- */
    {
        const int g = threadIdx.x >> 6;     /* 0..3 */
        const int c = threadIdx.x & 63;
        const size_t R0 = ((size_t)b*NPOINT + p0) * NSAMPLE;
        const float* Pb = points + (size_t)b*NDATA*CFEAT;
        const float* Xb = xyz    + (size_t)b*NDATA*3;

        for (int u0 = 0; u0 < ROWS_PG; u0 += GUNROLL) {
            int ids[GUNROLL];
#pragma unroll
            for (int u = 0; u < GUNROLL; u++)
                ids[u] = s_out[g*ROWS_PG + u0 + u];

            float v[GUNROLL];
#pragma unroll
            for (int u = 0; u < GUNROLL; u++)
                v[u] = __ldg(&Pb[(size_t)ids[u]*CFEAT + c]);
#pragma unroll
            for (int u = 0; u < GUNROLL; u++)
                out[(R0 + g*ROWS_PG + u0 + u)*67 + 3 + c] = v[u];

            if (c < 3) {
                float xv[GUNROLL];
#pragma unroll
                for (int u = 0; u < GUNROLL; u++)
                    xv[u] = __ldg(&Xb[(size_t)ids[u]*3 + c]);
#pragma unroll
                for (int u = 0; u < GUNROLL; u++) {
                    size_t r = R0 + g*ROWS_PG + u0 + u;
                    out[r*67 + c]         = xv[u];
                    out[GX_OFF + r*3 + c] = xv[u];
                }
            }
        }
    }
}

extern "C" void kernel_launch(void* const* d_in, const int* in_sizes, int n_in,
                              void* d_out, int out_size)
{
    const float *new_xyz = nullptr, *xyz = nullptr, *points = nullptr;
    for (int i = 0; i < n_in; i++) {
        if      (in_sizes[i] == BATCH*NPOINT*3)     new_xyz = (const float*)d_in[i];
        else if (in_sizes[i] == BATCH*NDATA*3)      xyz     = (const float*)d_in[i];
        else if (in_sizes[i] == BATCH*NDATA*CFEAT)  points  = (const float*)d_in[i];
    }
    float* out = (float*)d_out;

    k_transpose<<<(BATCH*NDATA + 255)/256, 256>>>(xyz);

    dim3 gs(NPOINT/QB, BATCH);
    k_search<<<gs, WPB*32>>>(new_xyz, xyz, points, out);
}

// round 14
// speedup vs baseline: 1.2241x; 1.1596x over previous
#include <cuda_runtime.h>

#define BATCH   8
#define NDATA   8192
#define NPOINT  1024
#define NSAMPLE 32
#define CFEAT   64
#define RADIUSF 0.2f
#define T_LOOSE 0.0404f

#define NP_SIZE  (BATCH*NPOINT*NSAMPLE*(3+CFEAT))   /* 17563648 */
#define IDX_OFF  NP_SIZE
#define IDX_SIZE (BATCH*NPOINT*NSAMPLE)             /* 262144 */
#define GX_OFF   (IDX_OFF + IDX_SIZE)

#define QB  8    /* queries per block             */
#define WPB 8    /* warps per block (scan chunks) */
#define CHUNK (NDATA/WPB)                           /* 1024 */
#define CAP 64   /* candidate capacity per query  */

#define ROWS_PB   (QB*NSAMPLE)                      /* 256 rows per block    */
#define ROWS_PG   (ROWS_PB/4)                       /* 64 rows per group     */
#define GUNROLL   8

__device__ float4 g_pts[BATCH*NDATA];   /* (x, y, z, |p|^2) */

__global__ void k_transpose(const float* __restrict__ xyz)
{
    int t = blockIdx.x * blockDim.x + threadIdx.x;
    if (t < BATCH*NDATA) {
        float x = xyz[3*t + 0];
        float y = xyz[3*t + 1];
        float z = xyz[3*t + 2];
        float pp = fmaf(x, x, fmaf(y, y, z*z));
        g_pts[t] = make_float4(x, y, z, pp);
    }
}

__global__ __launch_bounds__(WPB*32, 4)
void k_search(const float* __restrict__ new_xyz,
              const float* __restrict__ points,
              float* __restrict__ out)
{
    __shared__ float s_cd[QB][CAP];
    __shared__ int   s_ci[QB][CAP];
    __shared__ int   s_cnt[QB];
    __shared__ int   s_out[QB*NSAMPLE];            /* flat: row-local order */
    __shared__ float s_qx[QB], s_qy[QB], s_qz[QB];

    const int b    = blockIdx.y;
    const int w    = threadIdx.x >> 5;
    const int lane = threadIdx.x & 31;
    const int p0   = blockIdx.x * QB;

    if (threadIdx.x < QB) {
        s_cnt[threadIdx.x] = 0;
        const float* qp = new_xyz + ((size_t)b*NPOINT + p0 + threadIdx.x) * 3;
        s_qx[threadIdx.x] = qp[0];
        s_qy[threadIdx.x] = qp[1];
        s_qz[threadIdx.x] = qp[2];
    }
    __syncthreads();

    float nqx[QB], nqy[QB], nqz[QB], qt[QB];
#pragma unroll
    for (int q = 0; q < QB; q++) {
        float cx = s_qx[q], cy = s_qy[q], cz = s_qz[q];
        nqx[q] = -2.0f*cx; nqy[q] = -2.0f*cy; nqz[q] = -2.0f*cz;
        qt[q] = T_LOOSE - fmaf(cx,cx, fmaf(cy,cy, cz*cz));
    }

    const float4* pts = g_pts + b*NDATA;

    /* ---- scan: branchless mask hot loop, rare slow path ----------------- */
    const int ptEnd = (w+1)*CHUNK;
    for (int pt = w*CHUNK + lane; pt < ptEnd; pt += 32) {
        float4 P = pts[pt];
        unsigned m = 0;
#pragma unroll
        for (int q = 0; q < QB; q++) {
            float l = fmaf(P.x, nqx[q], fmaf(P.y, nqy[q], fmaf(P.z, nqz[q], P.w)));
            if (l < qt[q]) m |= (1u << q);
        }
        while (m) {
            int q = __ffs(m) - 1;
            m &= m - 1;
            float dx = P.x - s_qx[q];
            float dy = P.y - s_qy[q];
            float dz = P.z - s_qz[q];
            float e = __fadd_rn(__fadd_rn(__fmul_rn(dx,dx), __fmul_rn(dy,dy)),
                                __fmul_rn(dz,dz));
            float d = __fsqrt_rn(e);
            if (d < RADIUSF) {
                int slot = atomicAdd(&s_cnt[q], 1);
                if (slot < CAP) { s_cd[q][slot] = d; s_ci[q][slot] = pt; }
            }
        }
    }
    __syncthreads();

    /* ---- rank: warp w handles query w; writes idx region ---------------- */
    {
        const int q = w;
        const int n = min(s_cnt[q], CAP);
        const int p = p0 + q;

        if (n == 0) {
            float cx = s_qx[q], cy = s_qy[q], cz = s_qz[q];
            float bd = 3.4e38f; int bi = 0;
            for (int pt = lane; pt < NDATA; pt += 32) {
                float4 P = pts[pt];
                float dx = P.x - cx;
                float dy = P.y - cy;
                float dz = P.z - cz;
                float e  = __fadd_rn(__fadd_rn(__fmul_rn(dx,dx), __fmul_rn(dy,dy)),
                                     __fmul_rn(dz,dz));
                if (e < bd) { bd = e; bi = pt; }
            }
#pragma unroll
            for (int off = 16; off >= 1; off >>= 1) {
                float od = __shfl_xor_sync(0xffffffffu, bd, off);
                int   oi = __shfl_xor_sync(0xffffffffu, bi, off);
                if (od < bd || (od == bd && oi < bi)) { bd = od; bi = oi; }
            }
            s_out[q*NSAMPLE + lane] = bi;
        } else {
            for (int i = lane; i < n; i += 32) {
                float di = s_cd[q][i]; int ii = s_ci[q][i];
                int rank = 0;
                for (int j = 0; j < n; j++) {
                    float dj = s_cd[q][j]; int ij = s_ci[q][j];
                    rank += (dj < di) || (dj == di && ij < ii);
                }
                if (rank < NSAMPLE) s_out[q*NSAMPLE + rank] = ii;
            }
            __syncwarp();
            int nearest = s_out[q*NSAMPLE];
            if (lane >= n) s_out[q*NSAMPLE + lane] = nearest;
        }
        __syncwarp();

        out[IDX_OFF + ((size_t)(b*NPOINT + p))*NSAMPLE + lane]
            = (float)s_out[q*NSAMPLE + lane];
    }
    __syncthreads();

    /* ---- fused gather: this block's 256 consecutive output rows --------- */
    {
        const int g = threadIdx.x >> 6;     /* 0..3 */
        const int c = threadIdx.x & 63;
        const size_t R0 = ((size_t)b*NPOINT + p0) * NSAMPLE;
        const float* Pb  = points + (size_t)b*NDATA*CFEAT;
        float* onp = out + R0*67;           /* 64-bit once; int offsets after */
        float* ogx = out + GX_OFF + R0*3;

#pragma unroll
        for (int u0 = 0; u0 < ROWS_PG; u0 += GUNROLL) {
            int ids[GUNROLL];
#pragma unroll
            for (int u = 0; u < GUNROLL; u++)
                ids[u] = s_out[g*ROWS_PG + u0 + u];

            float v[GUNROLL];
#pragma unroll
            for (int u = 0; u < GUNROLL; u++)
                v[u] = __ldg(&Pb[ids[u]*CFEAT + c]);
#pragma unroll
            for (int u = 0; u < GUNROLL; u++)
                onp[(g*ROWS_PG + u0 + u)*67 + 3 + c] = v[u];

            if (c < 3) {
                float xv[GUNROLL];
#pragma unroll
                for (int u = 0; u < GUNROLL; u++) {
                    float4 Q = __ldg(&pts[ids[u]]);        /* L1 broadcast */
                    xv[u] = (c == 0) ? Q.x : ((c == 1) ? Q.y : Q.z);
                }
#pragma unroll
                for (int u = 0; u < GUNROLL; u++) {
                    int rr = g*ROWS_PG + u0 + u;
                    onp[rr*67 + c] = xv[u];
                    ogx[rr*3  + c] = xv[u];
                }
            }
        }
    }
}

extern "C" void kernel_launch(void* const* d_in, const int* in_sizes, int n_in,
                              void* d_out, int out_size)
{
    const float *new_xyz = nullptr, *xyz = nullptr, *points = nullptr;
    for (int i = 0; i < n_in; i++) {
        if      (in_sizes[i] == BATCH*NPOINT*3)     new_xyz = (const float*)d_in[i];
        else if (in_sizes[i] == BATCH*NDATA*3)      xyz     = (const float*)d_in[i];
        else if (in_sizes[i] == BATCH*NDATA*CFEAT)  points  = (const float*)d_in[i];
    }
    float* out = (float*)d_out;

    k_transpose<<<(BATCH*NDATA + 255)/256, 256>>>(xyz);

    dim3 gs(NPOINT/QB, BATCH);
    k_search<<<gs, WPB*32>>>(new_xyz, points, out);
}

// round 15
// speedup vs baseline: 1.3277x; 1.0846x over previous
#include <cuda_runtime.h>

#define BATCH   8
#define NDATA   8192
#define NPOINT  1024
#define NSAMPLE 32
#define CFEAT   64
#define RADIUSF 0.2f
#define T_LOOSE 0.0404f

#define NP_SIZE  (BATCH*NPOINT*NSAMPLE*(3+CFEAT))   /* 17563648 */
#define IDX_OFF  NP_SIZE
#define IDX_SIZE (BATCH*NPOINT*NSAMPLE)             /* 262144 */
#define GX_OFF   (IDX_OFF + IDX_SIZE)

#define QB  8    /* queries per block = warps per block */
#define WPB 8
#define CHUNK (NDATA/WPB)                           /* 1024 */
#define CAP 64   /* candidate capacity per query  */

__device__ float4 g_pts[BATCH*NDATA];   /* (x, y, z, |p|^2) */

__global__ void k_transpose(const float* __restrict__ xyz)
{
    int t = blockIdx.x * blockDim.x + threadIdx.x;
    if (t < BATCH*NDATA) {
        float x = xyz[3*t + 0];
        float y = xyz[3*t + 1];
        float z = xyz[3*t + 2];
        float pp = fmaf(x, x, fmaf(y, y, z*z));
        g_pts[t] = make_float4(x, y, z, pp);
    }
}

__global__ __launch_bounds__(WPB*32, 4)
void k_search(const float* __restrict__ new_xyz,
              const float* __restrict__ points,
              float* __restrict__ out)
{
    __shared__ float s_cd[QB][CAP];
    __shared__ int   s_ci[QB][CAP];
    __shared__ int   s_cnt[QB];
    __shared__ int   s_out[QB][NSAMPLE];
    __shared__ float s_qx[QB], s_qy[QB], s_qz[QB];

    const int b    = blockIdx.y;
    const int w    = threadIdx.x >> 5;
    const int lane = threadIdx.x & 31;
    const int p0   = blockIdx.x * QB;

    if (threadIdx.x < QB) {
        s_cnt[threadIdx.x] = 0;
        const float* qp = new_xyz + ((size_t)b*NPOINT + p0 + threadIdx.x) * 3;
        s_qx[threadIdx.x] = qp[0];
        s_qy[threadIdx.x] = qp[1];
        s_qz[threadIdx.x] = qp[2];
    }
    __syncthreads();

    float nqx[QB], nqy[QB], nqz[QB], qt[QB];
#pragma unroll
    for (int q = 0; q < QB; q++) {
        float cx = s_qx[q], cy = s_qy[q], cz = s_qz[q];
        nqx[q] = -2.0f*cx; nqy[q] = -2.0f*cy; nqz[q] = -2.0f*cz;
        qt[q] = T_LOOSE - fmaf(cx,cx, fmaf(cy,cy, cz*cz));
    }

    const float4* pts = g_pts + b*NDATA;

    /* ---- scan: branchless mask hot loop, rare slow path ----------------- */
    const int ptEnd = (w+1)*CHUNK;
    for (int pt = w*CHUNK + lane; pt < ptEnd; pt += 32) {
        float4 P = pts[pt];
        unsigned m = 0;
#pragma unroll
        for (int q = 0; q < QB; q++) {
            float l = fmaf(P.x, nqx[q], fmaf(P.y, nqy[q], fmaf(P.z, nqz[q], P.w)));
            if (l < qt[q]) m |= (1u << q);
        }
        while (m) {
            int q = __ffs(m) - 1;
            m &= m - 1;
            float dx = P.x - s_qx[q];
            float dy = P.y - s_qy[q];
            float dz = P.z - s_qz[q];
            float e = __fadd_rn(__fadd_rn(__fmul_rn(dx,dx), __fmul_rn(dy,dy)),
                                __fmul_rn(dz,dz));
            float d = __fsqrt_rn(e);
            if (d < RADIUSF) {
                int slot = atomicAdd(&s_cnt[q], 1);
                if (slot < CAP) { s_cd[q][slot] = d; s_ci[q][slot] = pt; }
            }
        }
    }
    __syncthreads();   /* only block-wide barrier: candidates complete */

    /* ---- rank + gather: fully warp-local, no further barriers ----------- */
    const int q = w;
    const int n = min(s_cnt[q], CAP);
    const size_t R0 = ((size_t)b*NPOINT + p0 + q) * NSAMPLE;

    if (n == 0) {
        /* rare: warp-local global argmin rescan (overlaps other warps' gathers) */
        float cx = s_qx[q], cy = s_qy[q], cz = s_qz[q];
        float bd = 3.4e38f; int bi = 0;
        for (int pt = lane; pt < NDATA; pt += 32) {
            float4 P = pts[pt];
            float dx = P.x - cx;
            float dy = P.y - cy;
            float dz = P.z - cz;
            float e  = __fadd_rn(__fadd_rn(__fmul_rn(dx,dx), __fmul_rn(dy,dy)),
                                 __fmul_rn(dz,dz));
            if (e < bd) { bd = e; bi = pt; }
        }
#pragma unroll
        for (int off = 16; off >= 1; off >>= 1) {
            float od = __shfl_xor_sync(0xffffffffu, bd, off);
            int   oi = __shfl_xor_sync(0xffffffffu, bi, off);
            if (od < bd || (od == bd && oi < bi)) { bd = od; bi = oi; }
        }
        s_out[q][lane] = bi;
    } else {
        for (int i = lane; i < n; i += 32) {
            float di = s_cd[q][i]; int ii = s_ci[q][i];
            int rank = 0;
            for (int j = 0; j < n; j++) {
                float dj = s_cd[q][j]; int ij = s_ci[q][j];
                rank += (dj < di) || (dj == di && ij < ii);
            }
            if (rank < NSAMPLE) s_out[q][rank] = ii;
        }
        __syncwarp();
        int nearest = s_out[q][0];
        if (lane >= n) s_out[q][lane] = nearest;
    }
    __syncwarp();

    out[IDX_OFF + R0 + lane] = (float)s_out[q][lane];

    /* gather this query's 32 rows: 4-row unroll, MLP=8 feature loads */
    {
        const float* Pb  = points + (size_t)b*NDATA*CFEAT;
        float* onp = out + R0*67;
        float* ogx = out + GX_OFF + R0*3;

#pragma unroll
        for (int r0 = 0; r0 < NSAMPLE; r0 += 4) {
            int ids[4];
#pragma unroll
            for (int u = 0; u < 4; u++) ids[u] = s_out[q][r0 + u];

            float v0[4], v1[4];
#pragma unroll
            for (int u = 0; u < 4; u++) {
                v0[u] = __ldg(&Pb[ids[u]*CFEAT + lane]);
                v1[u] = __ldg(&Pb[ids[u]*CFEAT + 32 + lane]);
            }
#pragma unroll
            for (int u = 0; u < 4; u++) {
                onp[(r0 + u)*67 + 3  + lane] = v0[u];
                onp[(r0 + u)*67 + 35 + lane] = v1[u];
            }
            if (lane < 3) {
                float xv[4];
#pragma unroll
                for (int u = 0; u < 4; u++) {
                    float4 Q = __ldg(&pts[ids[u]]);        /* L1 broadcast */
                    xv[u] = (lane == 0) ? Q.x : ((lane == 1) ? Q.y : Q.z);
                }
#pragma unroll
                for (int u = 0; u < 4; u++) {
                    onp[(r0 + u)*67 + lane] = xv[u];
                    ogx[(r0 + u)*3  + lane] = xv[u];
                }
            }
        }
    }
}

extern "C" void kernel_launch(void* const* d_in, const int* in_sizes, int n_in,
                              void* d_out, int out_size)
{
    const float *new_xyz = nullptr, *xyz = nullptr, *points = nullptr;
    for (int i = 0; i < n_in; i++) {
        if      (in_sizes[i] == BATCH*NPOINT*3)     new_xyz = (const float*)d_in[i];
        else if (in_sizes[i] == BATCH*NDATA*3)      xyz     = (const float*)d_in[i];
        else if (in_sizes[i] == BATCH*NDATA*CFEAT)  points  = (const float*)d_in[i];
    }
    float* out = (float*)d_out;

    k_transpose<<<(BATCH*NDATA + 255)/256, 256>>>(xyz);

    dim3 gs(NPOINT/QB, BATCH);
    k_search<<<gs, WPB*32>>>(new_xyz, points, out);
}